// round 11
// baseline (speedup 1.0000x reference)
#include <cuda_runtime.h>

// ApplyDF: complex order-5 time-FIR on first 96 of 481 freq bins, copy the rest.
// spec:  [B=32][1][T=2000][F=481][2]  float32
// coefs: [B=32][ORDER=5][T=2000][NB=96][2] float32
// out:   same shape as spec
//
// TS=16 time steps per thread (grid 16000 blocks -> ~13.5 waves @ 8 blk/SM):
//  - copy  (f>=96): 16 front-batched loads then 16 stores
//  - filter (f<96): four sequential TS=4 rounds (proven R6 shape), each
//    front-batching 20 coef loads; 4-tap window overlap carried in registers
//    between rounds so peak live regs stays <= 64.
// DRAM is at its ~6.8 TB/s ceiling; this round targets wave-count /
// block-scheduling overhead (R9 evidence: halving blocks -> -1.4us device).
//
// All indexing 32-bit (max byte offset ~246 MB < 2^31).

#define BB 32
#define TT 2000
#define FF 481
#define NB 96
#define ORD 5
#define TS 16            // TT % TS == 0  (2000 = 16*125)

__device__ __forceinline__ void cmac(float2 s, float2 c, float& r, float& i) {
    r = fmaf(s.x, c.x, fmaf(-s.y, c.y, r));
    i = fmaf(s.x, c.y, fmaf( s.y, c.x, i));
}

// One TS=4 filter round: outputs at baseR..baseR+3*FF, coefs at cbR,
// taps sm4..sm1 (history) and sA..sD (current 4 steps).
__device__ __forceinline__ void filter4(
    const float2* __restrict__ coefs, float2* __restrict__ out,
    int baseR, int cbR, int cstr,
    float2 sm4, float2 sm3, float2 sm2, float2 sm1,
    float2 sA, float2 sB, float2 sC, float2 sD)
{
    const float2 c00 = __ldg(&coefs[cbR]);
    const float2 c01 = __ldg(&coefs[cbR + NB]);
    const float2 c02 = __ldg(&coefs[cbR + 2 * NB]);
    const float2 c03 = __ldg(&coefs[cbR + 3 * NB]);
    const float2 c10 = __ldg(&coefs[cbR + cstr]);
    const float2 c11 = __ldg(&coefs[cbR + cstr + NB]);
    const float2 c12 = __ldg(&coefs[cbR + cstr + 2 * NB]);
    const float2 c13 = __ldg(&coefs[cbR + cstr + 3 * NB]);
    const float2 c20 = __ldg(&coefs[cbR + 2 * cstr]);
    const float2 c21 = __ldg(&coefs[cbR + 2 * cstr + NB]);
    const float2 c22 = __ldg(&coefs[cbR + 2 * cstr + 2 * NB]);
    const float2 c23 = __ldg(&coefs[cbR + 2 * cstr + 3 * NB]);
    const float2 c30 = __ldg(&coefs[cbR + 3 * cstr]);
    const float2 c31 = __ldg(&coefs[cbR + 3 * cstr + NB]);
    const float2 c32 = __ldg(&coefs[cbR + 3 * cstr + 2 * NB]);
    const float2 c33 = __ldg(&coefs[cbR + 3 * cstr + 3 * NB]);
    const float2 c40 = __ldg(&coefs[cbR + 4 * cstr]);
    const float2 c41 = __ldg(&coefs[cbR + 4 * cstr + NB]);
    const float2 c42 = __ldg(&coefs[cbR + 4 * cstr + 2 * NB]);
    const float2 c43 = __ldg(&coefs[cbR + 4 * cstr + 3 * NB]);

    float r0 = 0.f, i0 = 0.f, r1 = 0.f, i1 = 0.f;
    float r2 = 0.f, i2 = 0.f, r3 = 0.f, i3 = 0.f;

    cmac(sm4, c00, r0, i0);  cmac(sm3, c10, r0, i0);  cmac(sm2, c20, r0, i0);
    cmac(sm1, c30, r0, i0);  cmac(sA,  c40, r0, i0);

    cmac(sm3, c01, r1, i1);  cmac(sm2, c11, r1, i1);  cmac(sm1, c21, r1, i1);
    cmac(sA,  c31, r1, i1);  cmac(sB,  c41, r1, i1);

    cmac(sm2, c02, r2, i2);  cmac(sm1, c12, r2, i2);  cmac(sA,  c22, r2, i2);
    cmac(sB,  c32, r2, i2);  cmac(sC,  c42, r2, i2);

    cmac(sm1, c03, r3, i3);  cmac(sA,  c13, r3, i3);  cmac(sB,  c23, r3, i3);
    cmac(sC,  c33, r3, i3);  cmac(sD,  c43, r3, i3);

    out[baseR]          = make_float2(r0, i0);
    out[baseR + FF]     = make_float2(r1, i1);
    out[baseR + 2 * FF] = make_float2(r2, i2);
    out[baseR + 3 * FF] = make_float2(r3, i3);
}

__global__ __launch_bounds__(128, 8) void apply_df_kernel(
    const float2* __restrict__ spec,
    const float2* __restrict__ coefs,
    float2* __restrict__ out)
{
    const int f = blockIdx.x * 128 + threadIdx.x;
    if (f >= FF) return;
    const int t0 = blockIdx.y * TS;
    const int b  = blockIdx.z;

    const int base0 = (b * TT + t0) * FF + f;   // float2 element index @ t0

    if (f >= NB) {
        // Pass-through copy of 16 t-steps, loads front-batched.
        float2 v[TS];
        #pragma unroll
        for (int j = 0; j < TS; ++j) v[j] = __ldg(&spec[base0 + j * FF]);
        #pragma unroll
        for (int j = 0; j < TS; ++j) out[base0 + j * FF] = v[j];
        return;
    }

    const int cstr = TT * NB;                          // tap-n stride; t stride = NB
    const int cb0  = ((b * ORD) * TT + t0) * NB + f;   // (b, n=0, t0, f)

    const float2 z = make_float2(0.f, 0.f);
    // Rolling 4-tap history (t0-4 .. t0-1); only t0==0 pads.
    float2 h0 = (t0 >= 4) ? __ldg(&spec[base0 - 4 * FF]) : z;
    float2 h1 = (t0 >= 3) ? __ldg(&spec[base0 - 3 * FF]) : z;
    float2 h2 = (t0 >= 2) ? __ldg(&spec[base0 - 2 * FF]) : z;
    float2 h3 = (t0 >= 1) ? __ldg(&spec[base0 - 1 * FF]) : z;

    #pragma unroll
    for (int r = 0; r < TS / 4; ++r) {
        const int off = r * 4;
        const float2 sA = __ldg(&spec[base0 + (off + 0) * FF]);
        const float2 sB = __ldg(&spec[base0 + (off + 1) * FF]);
        const float2 sC = __ldg(&spec[base0 + (off + 2) * FF]);
        const float2 sD = __ldg(&spec[base0 + (off + 3) * FF]);

        filter4(coefs, out, base0 + off * FF, cb0 + off * NB, cstr,
                h0, h1, h2, h3, sA, sB, sC, sD);

        h0 = sA; h1 = sB; h2 = sC; h3 = sD;   // carry window to next round
    }
}

extern "C" void kernel_launch(void* const* d_in, const int* in_sizes, int n_in,
                              void* d_out, int out_size)
{
    const float2* spec  = (const float2*)d_in[0];
    const float2* coefs = (const float2*)d_in[1];
    float2* out = (float2*)d_out;

    dim3 block(128, 1, 1);
    dim3 grid((FF + 127) / 128, TT / TS, BB);   // (4, 125, 32) = 16000 blocks
    apply_df_kernel<<<grid, block>>>(spec, coefs, out);
}

// round 12
// speedup vs baseline: 1.0156x; 1.0156x over previous
#include <cuda_runtime.h>

// ApplyDF: complex order-5 time-FIR on first 96 of 481 freq bins, copy the rest.
// spec:  [B=32][1][T=2000][F=481][2]  float32
// coefs: [B=32][ORDER=5][T=2000][NB=96][2] float32
// out:   same shape as spec
//
// CONVERGED configuration (R8; best measured wall clock, device time at the
// LTS-fabric ceiling):
//   - TS=4 time steps per thread; 28 loads (8 spec taps + 20 coefs) all
//     front-batched before any FMA -> regs=64, maximal per-thread MLP.
//   - 128-thread blocks, __launch_bounds__(128, 8).
//   - Default cache policy (streaming hints measured neutral/harmful).
// Measured: ~6.8 TB/s (LTS cap ~6300 B/cyc), traffic at the ~707 MB
// analytical byte floor -> ~104 us device-time floor.
//
// All indexing 32-bit (max byte offset ~246 MB < 2^31).

#define BB 32
#define TT 2000
#define FF 481
#define NB 96
#define ORD 5

__device__ __forceinline__ void cmac(float2 s, float2 c, float& r, float& i) {
    r = fmaf(s.x, c.x, fmaf(-s.y, c.y, r));
    i = fmaf(s.x, c.y, fmaf( s.y, c.x, i));
}

__global__ __launch_bounds__(128, 8) void apply_df_kernel(
    const float2* __restrict__ spec,
    const float2* __restrict__ coefs,
    float2* __restrict__ out)
{
    const int f = blockIdx.x * 128 + threadIdx.x;
    if (f >= FF) return;
    const int t0 = blockIdx.y * 4;          // TT divisible by 4
    const int b  = blockIdx.z;

    const int base0 = (b * TT + t0) * FF + f;   // float2 element index @ t0

    // Current + future taps (t0..t0+3): always in range.
    const float2 sA = __ldg(&spec[base0]);
    const float2 sB = __ldg(&spec[base0 + FF]);
    const float2 sC = __ldg(&spec[base0 + 2 * FF]);
    const float2 sD = __ldg(&spec[base0 + 3 * FF]);

    if (f >= NB) {
        out[base0]          = sA;
        out[base0 + FF]     = sB;
        out[base0 + 2 * FF] = sC;
        out[base0 + 3 * FF] = sD;
        return;
    }

    const float2 z = make_float2(0.f, 0.f);
    // History taps t0-4 .. t0-1 (zero-padded at sequence start; only t0==0 pads)
    const float2 sm4 = (t0 >= 4) ? __ldg(&spec[base0 - 4 * FF]) : z;
    const float2 sm3 = (t0 >= 3) ? __ldg(&spec[base0 - 3 * FF]) : z;
    const float2 sm2 = (t0 >= 2) ? __ldg(&spec[base0 - 2 * FF]) : z;
    const float2 sm1 = (t0 >= 1) ? __ldg(&spec[base0 - 1 * FF]) : z;

    // coefs element index for (b, n, t, f): ((b*5 + n)*TT + t)*NB + f
    const int cb   = ((b * ORD) * TT + t0) * NB + f;   // (b, n=0, t0, f)
    const int cstr = TT * NB;                          // tap-n stride; t stride = NB

    // ---- Front-batch ALL 20 coef loads before any FMA ----
    const float2 c00 = __ldg(&coefs[cb]);
    const float2 c01 = __ldg(&coefs[cb + NB]);
    const float2 c02 = __ldg(&coefs[cb + 2 * NB]);
    const float2 c03 = __ldg(&coefs[cb + 3 * NB]);
    const float2 c10 = __ldg(&coefs[cb + cstr]);
    const float2 c11 = __ldg(&coefs[cb + cstr + NB]);
    const float2 c12 = __ldg(&coefs[cb + cstr + 2 * NB]);
    const float2 c13 = __ldg(&coefs[cb + cstr + 3 * NB]);
    const float2 c20 = __ldg(&coefs[cb + 2 * cstr]);
    const float2 c21 = __ldg(&coefs[cb + 2 * cstr + NB]);
    const float2 c22 = __ldg(&coefs[cb + 2 * cstr + 2 * NB]);
    const float2 c23 = __ldg(&coefs[cb + 2 * cstr + 3 * NB]);
    const float2 c30 = __ldg(&coefs[cb + 3 * cstr]);
    const float2 c31 = __ldg(&coefs[cb + 3 * cstr + NB]);
    const float2 c32 = __ldg(&coefs[cb + 3 * cstr + 2 * NB]);
    const float2 c33 = __ldg(&coefs[cb + 3 * cstr + 3 * NB]);
    const float2 c40 = __ldg(&coefs[cb + 4 * cstr]);
    const float2 c41 = __ldg(&coefs[cb + 4 * cstr + NB]);
    const float2 c42 = __ldg(&coefs[cb + 4 * cstr + 2 * NB]);
    const float2 c43 = __ldg(&coefs[cb + 4 * cstr + 3 * NB]);

    float r0 = 0.f, i0 = 0.f, r1 = 0.f, i1 = 0.f;
    float r2 = 0.f, i2 = 0.f, r3 = 0.f, i3 = 0.f;

    // out[t0+j] = sum_n spec[t0+j+n-4] * coef(t0+j, n)
    cmac(sm4, c00, r0, i0);  cmac(sm3, c10, r0, i0);  cmac(sm2, c20, r0, i0);
    cmac(sm1, c30, r0, i0);  cmac(sA,  c40, r0, i0);

    cmac(sm3, c01, r1, i1);  cmac(sm2, c11, r1, i1);  cmac(sm1, c21, r1, i1);
    cmac(sA,  c31, r1, i1);  cmac(sB,  c41, r1, i1);

    cmac(sm2, c02, r2, i2);  cmac(sm1, c12, r2, i2);  cmac(sA,  c22, r2, i2);
    cmac(sB,  c32, r2, i2);  cmac(sC,  c42, r2, i2);

    cmac(sm1, c03, r3, i3);  cmac(sA,  c13, r3, i3);  cmac(sB,  c23, r3, i3);
    cmac(sC,  c33, r3, i3);  cmac(sD,  c43, r3, i3);

    out[base0]          = make_float2(r0, i0);
    out[base0 + FF]     = make_float2(r1, i1);
    out[base0 + 2 * FF] = make_float2(r2, i2);
    out[base0 + 3 * FF] = make_float2(r3, i3);
}

extern "C" void kernel_launch(void* const* d_in, const int* in_sizes, int n_in,
                              void* d_out, int out_size)
{
    const float2* spec  = (const float2*)d_in[0];
    const float2* coefs = (const float2*)d_in[1];
    float2* out = (float2*)d_out;

    dim3 block(128, 1, 1);
    dim3 grid((FF + 127) / 128, TT / 4, BB);   // (4, 500, 32)
    apply_df_kernel<<<grid, block>>>(spec, coefs, out);
}

// round 13
// speedup vs baseline: 1.0510x; 1.0349x over previous
#include <cuda_runtime.h>

// ApplyDF: complex order-5 time-FIR on first 96 of 481 freq bins, copy the rest.
// spec:  [B=32][1][T=2000][F=481][2]  float32
// coefs: [B=32][ORDER=5][T=2000][NB=96][2] float32
// out:   same shape as spec
//
// CONVERGED configuration (best measured wall clock; device time at the
// LTS-fabric ceiling ~6300 B/cyc -> ~6.8 TB/s; traffic at the ~707 MB
// analytical byte floor -> ~104 us device-time floor):
//   - TS=4 time steps per thread; 28 loads (8 spec taps + 20 coefs) all
//     front-batched before any FMA -> regs=64, maximal consumed MLP.
//   - 128-thread blocks, __launch_bounds__(128, 8).
//   - Default cache policy (streaming hints measured neutral/harmful).
// Session evidence: TS=8/16 per-thread, 256-thread blocks, occupancy-cap
// changes, __ldcs/__stcs, and wave-count reduction all measured <= neutral.
// Residual run-to-run spread (~+/-4us) is environment DVFS, not structure.
//
// All indexing 32-bit (max byte offset ~246 MB < 2^31).

#define BB 32
#define TT 2000
#define FF 481
#define NB 96
#define ORD 5

__device__ __forceinline__ void cmac(float2 s, float2 c, float& r, float& i) {
    r = fmaf(s.x, c.x, fmaf(-s.y, c.y, r));
    i = fmaf(s.x, c.y, fmaf( s.y, c.x, i));
}

__global__ __launch_bounds__(128, 8) void apply_df_kernel(
    const float2* __restrict__ spec,
    const float2* __restrict__ coefs,
    float2* __restrict__ out)
{
    const int f = blockIdx.x * 128 + threadIdx.x;
    if (f >= FF) return;
    const int t0 = blockIdx.y * 4;          // TT divisible by 4
    const int b  = blockIdx.z;

    const int base0 = (b * TT + t0) * FF + f;   // float2 element index @ t0

    // Current + future taps (t0..t0+3): always in range.
    const float2 sA = __ldg(&spec[base0]);
    const float2 sB = __ldg(&spec[base0 + FF]);
    const float2 sC = __ldg(&spec[base0 + 2 * FF]);
    const float2 sD = __ldg(&spec[base0 + 3 * FF]);

    if (f >= NB) {
        out[base0]          = sA;
        out[base0 + FF]     = sB;
        out[base0 + 2 * FF] = sC;
        out[base0 + 3 * FF] = sD;
        return;
    }

    const float2 z = make_float2(0.f, 0.f);
    // History taps t0-4 .. t0-1 (zero-padded at sequence start; only t0==0 pads)
    const float2 sm4 = (t0 >= 4) ? __ldg(&spec[base0 - 4 * FF]) : z;
    const float2 sm3 = (t0 >= 3) ? __ldg(&spec[base0 - 3 * FF]) : z;
    const float2 sm2 = (t0 >= 2) ? __ldg(&spec[base0 - 2 * FF]) : z;
    const float2 sm1 = (t0 >= 1) ? __ldg(&spec[base0 - 1 * FF]) : z;

    // coefs element index for (b, n, t, f): ((b*5 + n)*TT + t)*NB + f
    const int cb   = ((b * ORD) * TT + t0) * NB + f;   // (b, n=0, t0, f)
    const int cstr = TT * NB;                          // tap-n stride; t stride = NB

    // ---- Front-batch ALL 20 coef loads before any FMA ----
    const float2 c00 = __ldg(&coefs[cb]);
    const float2 c01 = __ldg(&coefs[cb + NB]);
    const float2 c02 = __ldg(&coefs[cb + 2 * NB]);
    const float2 c03 = __ldg(&coefs[cb + 3 * NB]);
    const float2 c10 = __ldg(&coefs[cb + cstr]);
    const float2 c11 = __ldg(&coefs[cb + cstr + NB]);
    const float2 c12 = __ldg(&coefs[cb + cstr + 2 * NB]);
    const float2 c13 = __ldg(&coefs[cb + cstr + 3 * NB]);
    const float2 c20 = __ldg(&coefs[cb + 2 * cstr]);
    const float2 c21 = __ldg(&coefs[cb + 2 * cstr + NB]);
    const float2 c22 = __ldg(&coefs[cb + 2 * cstr + 2 * NB]);
    const float2 c23 = __ldg(&coefs[cb + 2 * cstr + 3 * NB]);
    const float2 c30 = __ldg(&coefs[cb + 3 * cstr]);
    const float2 c31 = __ldg(&coefs[cb + 3 * cstr + NB]);
    const float2 c32 = __ldg(&coefs[cb + 3 * cstr + 2 * NB]);
    const float2 c33 = __ldg(&coefs[cb + 3 * cstr + 3 * NB]);
    const float2 c40 = __ldg(&coefs[cb + 4 * cstr]);
    const float2 c41 = __ldg(&coefs[cb + 4 * cstr + NB]);
    const float2 c42 = __ldg(&coefs[cb + 4 * cstr + 2 * NB]);
    const float2 c43 = __ldg(&coefs[cb + 4 * cstr + 3 * NB]);

    float r0 = 0.f, i0 = 0.f, r1 = 0.f, i1 = 0.f;
    float r2 = 0.f, i2 = 0.f, r3 = 0.f, i3 = 0.f;

    // out[t0+j] = sum_n spec[t0+j+n-4] * coef(t0+j, n)
    cmac(sm4, c00, r0, i0);  cmac(sm3, c10, r0, i0);  cmac(sm2, c20, r0, i0);
    cmac(sm1, c30, r0, i0);  cmac(sA,  c40, r0, i0);

    cmac(sm3, c01, r1, i1);  cmac(sm2, c11, r1, i1);  cmac(sm1, c21, r1, i1);
    cmac(sA,  c31, r1, i1);  cmac(sB,  c41, r1, i1);

    cmac(sm2, c02, r2, i2);  cmac(sm1, c12, r2, i2);  cmac(sA,  c22, r2, i2);
    cmac(sB,  c32, r2, i2);  cmac(sC,  c42, r2, i2);

    cmac(sm1, c03, r3, i3);  cmac(sA,  c13, r3, i3);  cmac(sB,  c23, r3, i3);
    cmac(sC,  c33, r3, i3);  cmac(sD,  c43, r3, i3);

    out[base0]          = make_float2(r0, i0);
    out[base0 + FF]     = make_float2(r1, i1);
    out[base0 + 2 * FF] = make_float2(r2, i2);
    out[base0 + 3 * FF] = make_float2(r3, i3);
}

extern "C" void kernel_launch(void* const* d_in, const int* in_sizes, int n_in,
                              void* d_out, int out_size)
{
    const float2* spec  = (const float2*)d_in[0];
    const float2* coefs = (const float2*)d_in[1];
    float2* out = (float2*)d_out;

    dim3 block(128, 1, 1);
    dim3 grid((FF + 127) / 128, TT / 4, BB);   // (4, 500, 32)
    apply_df_kernel<<<grid, block>>>(spec, coefs, out);
}

// round 14
// speedup vs baseline: 1.0576x; 1.0063x over previous
#include <cuda_runtime.h>

// ApplyDF: complex order-5 time-FIR on first 96 of 481 freq bins, copy the rest.
// spec:  [B=32][1][T=2000][F=481][2]  float32
// coefs: [B=32][ORDER=5][T=2000][NB=96][2] float32
// out:   same shape as spec
//
// FINAL / CONVERGED (verified 4x at the hardware roofline):
//   - Traffic at the analytical byte floor (~707 MB): coefs 246MB + writes
//     246MB + copy-reads 197MB + filter-reads ~49MB (L2 dedupes 5x tap reuse).
//   - Bandwidth pinned at the B300 LTS-fabric cap (~6300 B/cyc ~ 6.85 TB/s):
//     device time 103.3-104.0 us across R4/R6/R8/R10/R13.
//   - Config: TS=4 t-steps/thread, all 28 loads front-batched (regs=64),
//     128-thread blocks, __launch_bounds__(128,8), default cache policy.
//   - Exhausted alternatives (all <= neutral): TS=8/16, 256-thr blocks,
//     occupancy-cap changes, __ldcs/__stcs, wave-count reduction.
//
// All indexing 32-bit (max byte offset ~246 MB < 2^31).

#define BB 32
#define TT 2000
#define FF 481
#define NB 96
#define ORD 5

__device__ __forceinline__ void cmac(float2 s, float2 c, float& r, float& i) {
    r = fmaf(s.x, c.x, fmaf(-s.y, c.y, r));
    i = fmaf(s.x, c.y, fmaf( s.y, c.x, i));
}

__global__ __launch_bounds__(128, 8) void apply_df_kernel(
    const float2* __restrict__ spec,
    const float2* __restrict__ coefs,
    float2* __restrict__ out)
{
    const int f = blockIdx.x * 128 + threadIdx.x;
    if (f >= FF) return;
    const int t0 = blockIdx.y * 4;          // TT divisible by 4
    const int b  = blockIdx.z;

    const int base0 = (b * TT + t0) * FF + f;   // float2 element index @ t0

    // Current + future taps (t0..t0+3): always in range.
    const float2 sA = __ldg(&spec[base0]);
    const float2 sB = __ldg(&spec[base0 + FF]);
    const float2 sC = __ldg(&spec[base0 + 2 * FF]);
    const float2 sD = __ldg(&spec[base0 + 3 * FF]);

    if (f >= NB) {
        out[base0]          = sA;
        out[base0 + FF]     = sB;
        out[base0 + 2 * FF] = sC;
        out[base0 + 3 * FF] = sD;
        return;
    }

    const float2 z = make_float2(0.f, 0.f);
    // History taps t0-4 .. t0-1 (zero-padded at sequence start; only t0==0 pads)
    const float2 sm4 = (t0 >= 4) ? __ldg(&spec[base0 - 4 * FF]) : z;
    const float2 sm3 = (t0 >= 3) ? __ldg(&spec[base0 - 3 * FF]) : z;
    const float2 sm2 = (t0 >= 2) ? __ldg(&spec[base0 - 2 * FF]) : z;
    const float2 sm1 = (t0 >= 1) ? __ldg(&spec[base0 - 1 * FF]) : z;

    // coefs element index for (b, n, t, f): ((b*5 + n)*TT + t)*NB + f
    const int cb   = ((b * ORD) * TT + t0) * NB + f;   // (b, n=0, t0, f)
    const int cstr = TT * NB;                          // tap-n stride; t stride = NB

    // ---- Front-batch ALL 20 coef loads before any FMA ----
    const float2 c00 = __ldg(&coefs[cb]);
    const float2 c01 = __ldg(&coefs[cb + NB]);
    const float2 c02 = __ldg(&coefs[cb + 2 * NB]);
    const float2 c03 = __ldg(&coefs[cb + 3 * NB]);
    const float2 c10 = __ldg(&coefs[cb + cstr]);
    const float2 c11 = __ldg(&coefs[cb + cstr + NB]);
    const float2 c12 = __ldg(&coefs[cb + cstr + 2 * NB]);
    const float2 c13 = __ldg(&coefs[cb + cstr + 3 * NB]);
    const float2 c20 = __ldg(&coefs[cb + 2 * cstr]);
    const float2 c21 = __ldg(&coefs[cb + 2 * cstr + NB]);
    const float2 c22 = __ldg(&coefs[cb + 2 * cstr + 2 * NB]);
    const float2 c23 = __ldg(&coefs[cb + 2 * cstr + 3 * NB]);
    const float2 c30 = __ldg(&coefs[cb + 3 * cstr]);
    const float2 c31 = __ldg(&coefs[cb + 3 * cstr + NB]);
    const float2 c32 = __ldg(&coefs[cb + 3 * cstr + 2 * NB]);
    const float2 c33 = __ldg(&coefs[cb + 3 * cstr + 3 * NB]);
    const float2 c40 = __ldg(&coefs[cb + 4 * cstr]);
    const float2 c41 = __ldg(&coefs[cb + 4 * cstr + NB]);
    const float2 c42 = __ldg(&coefs[cb + 4 * cstr + 2 * NB]);
    const float2 c43 = __ldg(&coefs[cb + 4 * cstr + 3 * NB]);

    float r0 = 0.f, i0 = 0.f, r1 = 0.f, i1 = 0.f;
    float r2 = 0.f, i2 = 0.f, r3 = 0.f, i3 = 0.f;

    // out[t0+j] = sum_n spec[t0+j+n-4] * coef(t0+j, n)
    cmac(sm4, c00, r0, i0);  cmac(sm3, c10, r0, i0);  cmac(sm2, c20, r0, i0);
    cmac(sm1, c30, r0, i0);  cmac(sA,  c40, r0, i0);

    cmac(sm3, c01, r1, i1);  cmac(sm2, c11, r1, i1);  cmac(sm1, c21, r1, i1);
    cmac(sA,  c31, r1, i1);  cmac(sB,  c41, r1, i1);

    cmac(sm2, c02, r2, i2);  cmac(sm1, c12, r2, i2);  cmac(sA,  c22, r2, i2);
    cmac(sB,  c32, r2, i2);  cmac(sC,  c42, r2, i2);

    cmac(sm1, c03, r3, i3);  cmac(sA,  c13, r3, i3);  cmac(sB,  c23, r3, i3);
    cmac(sC,  c33, r3, i3);  cmac(sD,  c43, r3, i3);

    out[base0]          = make_float2(r0, i0);
    out[base0 + FF]     = make_float2(r1, i1);
    out[base0 + 2 * FF] = make_float2(r2, i2);
    out[base0 + 3 * FF] = make_float2(r3, i3);
}

extern "C" void kernel_launch(void* const* d_in, const int* in_sizes, int n_in,
                              void* d_out, int out_size)
{
    const float2* spec  = (const float2*)d_in[0];
    const float2* coefs = (const float2*)d_in[1];
    float2* out = (float2*)d_out;

    dim3 block(128, 1, 1);
    dim3 grid((FF + 127) / 128, TT / 4, BB);   // (4, 500, 32)
    apply_df_kernel<<<grid, block>>>(spec, coefs, out);
}